// round 7
// baseline (speedup 1.0000x reference)
#include <cuda_runtime.h>
#include <cuda_bf16.h>
#include <cstdint>

#define TPB  512
#define GRID 148

// ---- dynamic shared memory layout (bytes) ----
// h1 tiles: 128 rows x 128 bf16, padded row stride 272 B (conflict-free ldmatrix)
#define H1_STRIDE 272
#define H1A_OFF   0
#define H1B_OFF   34816                    // 128*272
#define PA_OFF    69632                    // 16 warps x 128 rows x f32   (8192)
#define PB_OFF    77824                    // 16 warps x 3 ch x 128 x f32 (24576)
#define SMEM_TOTAL 102400

static __device__ __forceinline__ uint32_t smem_u32(const void* p) {
    uint32_t a;
    asm("{ .reg .u64 t; cvta.to.shared.u64 t, %1; cvt.u32.u64 %0, t; }" : "=r"(a) : "l"(p));
    return a;
}

static __device__ __forceinline__ uint32_t pack_bf16(float a, float b) {
    __nv_bfloat162 t = __floats2bfloat162_rn(a, b);
    return *reinterpret_cast<uint32_t*>(&t);
}

static __device__ __forceinline__ void ldsm_x4(uint32_t a[4], uint32_t addr) {
    asm volatile("ldmatrix.sync.aligned.m8n8.x4.shared.b16 {%0,%1,%2,%3}, [%4];"
                 : "=r"(a[0]), "=r"(a[1]), "=r"(a[2]), "=r"(a[3]) : "r"(addr));
}

static __device__ __forceinline__ void mma16816(float c[4], const uint32_t a[4],
                                                uint32_t b0, uint32_t b1) {
    asm volatile(
        "mma.sync.aligned.m16n8k16.row.col.f32.bf16.bf16.f32 "
        "{%0,%1,%2,%3}, {%4,%5,%6,%7}, {%8,%9}, {%0,%1,%2,%3};"
        : "+f"(c[0]), "+f"(c[1]), "+f"(c[2]), "+f"(c[3])
        : "r"(a[0]), "r"(a[1]), "r"(a[2]), "r"(a[3]), "r"(b0), "r"(b1));
}

__global__ void __launch_bounds__(TPB, 1) KroneNet_59485297049802_kernel(
    const float* __restrict__ x,
    const float* __restrict__ w1a, const float* __restrict__ w1b,
    const float* __restrict__ b1a, const float* __restrict__ b1b,
    const float* __restrict__ w2a, const float* __restrict__ w2b,
    const float* __restrict__ b2a, const float* __restrict__ b2b,
    const float* __restrict__ w3a, const float* __restrict__ w3b,
    const float* __restrict__ b3a, const float* __restrict__ b3b,
    float* __restrict__ out, int Bn)
{
    extern __shared__ __align__(16) char sm[];
    const uint32_t smb = smem_u32(sm);
    const int tid  = threadIdx.x;
    const int wid  = tid >> 5;     // 0..15, warp owns columns [8*wid, 8*wid+8)
    const int lane = tid & 31;
    const int quad = lane >> 2;    // 0..7
    const int qlid = lane & 3;     // 0..3

    float* pA = reinterpret_cast<float*>(sm + PA_OFF);
    float* pB = reinterpret_cast<float*>(sm + PB_OFF);

    // ---- persistent B fragments: W2 (row-major [n][k]) -> bf16 mma B operand ----
    // n = 8*wid + quad ; per k-step kk: b0 = {W2[n][k0],W2[n][k0+1]}, b1 = k0+8
    uint32_t BfA[8][2], BfB[8][2];
    {
        const int n = 8 * wid + quad;
        #pragma unroll
        for (int kk = 0; kk < 8; ++kk) {
            const int k0 = 16 * kk + 2 * qlid;
            float2 lo = *reinterpret_cast<const float2*>(w2a + n * 128 + k0);
            float2 hi = *reinterpret_cast<const float2*>(w2a + n * 128 + k0 + 8);
            BfA[kk][0] = pack_bf16(lo.x, lo.y);
            BfA[kk][1] = pack_bf16(hi.x, hi.y);
            lo = *reinterpret_cast<const float2*>(w2b + n * 128 + k0);
            hi = *reinterpret_cast<const float2*>(w2b + n * 128 + k0 + 8);
            BfB[kk][0] = pack_bf16(lo.x, lo.y);
            BfB[kk][1] = pack_bf16(hi.x, hi.y);
        }
    }

    // ---- epilogue constants for this thread's D columns: n = 8*wid + 2*qlid + h ----
    float baC[2], waC[2], bbC[2], wbC[3][2];
    #pragma unroll
    for (int h = 0; h < 2; ++h) {
        const int n = 8 * wid + 2 * qlid + h;
        baC[h] = b2a[n];
        waC[h] = w3a[n];
        bbC[h] = b2b[n];
        wbC[0][h] = w3b[n];
        wbC[1][h] = w3b[128 + n];
        wbC[2][h] = w3b[256 + n];
    }
    const float s_b3a = b3a[0];
    const float s_b3b0 = b3b[0], s_b3b1 = b3b[1], s_b3b2 = b3b[2];

    // ---- per-lane layer-1 weights: lane l owns k in {2l, 2l+1, 64+2l, 65+2l} ----
    float A0[4], A1[4], Ab[4], Bw0[4], Bw1[4], Bb[4];
    #pragma unroll
    for (int jj = 0; jj < 4; ++jj) {
        const int k = ((jj >> 1) << 6) + 2 * lane + (jj & 1);
        A0[jj]  = w1a[2 * k]; A1[jj]  = w1a[2 * k + 1]; Ab[jj] = b1a[k];
        Bw0[jj] = w1b[2 * k]; Bw1[jj] = w1b[2 * k + 1]; Bb[jj] = b1b[k];
    }

    // ldmatrix per-lane source address offset (m8n8.x4 over 16 rows x 16 cols bf16)
    const uint32_t lrow  = (uint32_t)((lane & 7) + ((lane >> 3) & 1) * 8);
    const uint32_t lcolb = (uint32_t)(((lane >> 4) & 1) * 16);
    const uint32_t aA = smb + H1A_OFF + lrow * H1_STRIDE + lcolb;
    const uint32_t aB = smb + H1B_OFF + lrow * H1_STRIDE + lcolb;

    const int ntiles = Bn >> 7;
    const float2* x2 = reinterpret_cast<const float2*>(x);

    for (int t = blockIdx.x; t < ntiles; t += gridDim.x) {
        // ---- layer 1: h1 = relu(W1 x + b1) -> bf16 SMEM (warp w: rows 8w..8w+7) ----
        #pragma unroll
        for (int r = 0; r < 8; ++r) {
            const int row = wid * 8 + r;
            const int rg  = t * 128 + row;
            const float2 xa = x2[rg];
            const float2 xb = x2[Bn + rg];
            float ha[4], hb[4];
            #pragma unroll
            for (int jj = 0; jj < 4; ++jj) {
                ha[jj] = fmaxf(fmaf(xa.x, A0[jj],  fmaf(xa.y, A1[jj],  Ab[jj])), 0.f);
                hb[jj] = fmaxf(fmaf(xb.x, Bw0[jj], fmaf(xb.y, Bw1[jj], Bb[jj])), 0.f);
            }
            char* rowa = sm + H1A_OFF + row * H1_STRIDE;
            char* rowb = sm + H1B_OFF + row * H1_STRIDE;
            *reinterpret_cast<uint32_t*>(rowa + 4 * lane)       = pack_bf16(ha[0], ha[1]);
            *reinterpret_cast<uint32_t*>(rowa + 128 + 4 * lane) = pack_bf16(ha[2], ha[3]);
            *reinterpret_cast<uint32_t*>(rowb + 4 * lane)       = pack_bf16(hb[0], hb[1]);
            *reinterpret_cast<uint32_t*>(rowb + 128 + 4 * lane) = pack_bf16(hb[2], hb[3]);
        }
        __syncthreads();

        // ---- layer 2 (HMMA, both streams fused) + in-register epilogue ----
        #pragma unroll
        for (int i = 0; i < 8; ++i) {
            const uint32_t ibaseA = aA + (uint32_t)(i * 16 * H1_STRIDE);
            const uint32_t ibaseB = aB + (uint32_t)(i * 16 * H1_STRIDE);

            float ca[4] = {0.f, 0.f, 0.f, 0.f};
            float cb[4] = {0.f, 0.f, 0.f, 0.f};
            #pragma unroll
            for (int kk = 0; kk < 8; ++kk) {
                uint32_t afA[4], afB[4];
                ldsm_x4(afA, ibaseA + 32u * kk);
                ldsm_x4(afB, ibaseB + 32u * kk);
                mma16816(ca, afA, BfA[kk][0], BfA[kk][1]);
                mma16816(cb, afB, BfB[kk][0], BfB[kk][1]);
            }

            // stream a: relu(+b2a) dot w3a over this thread's 2 cols
            float p0 = fmaxf(ca[0] + baC[0], 0.f) * waC[0]
                     + fmaxf(ca[1] + baC[1], 0.f) * waC[1];
            float p1 = fmaxf(ca[2] + baC[0], 0.f) * waC[0]
                     + fmaxf(ca[3] + baC[1], 0.f) * waC[1];
            p0 += __shfl_xor_sync(0xFFFFFFFFu, p0, 1);
            p0 += __shfl_xor_sync(0xFFFFFFFFu, p0, 2);
            p1 += __shfl_xor_sync(0xFFFFFFFFu, p1, 1);
            p1 += __shfl_xor_sync(0xFFFFFFFFu, p1, 2);

            // stream b: relu(+b2b), then 3-channel dot with w3b
            const float v0 = fmaxf(cb[0] + bbC[0], 0.f);
            const float v1 = fmaxf(cb[1] + bbC[1], 0.f);
            const float u0 = fmaxf(cb[2] + bbC[0], 0.f);
            const float u1 = fmaxf(cb[3] + bbC[1], 0.f);
            float q0[3], q1[3];
            #pragma unroll
            for (int c = 0; c < 3; ++c) {
                float s0 = v0 * wbC[c][0] + v1 * wbC[c][1];
                float s1 = u0 * wbC[c][0] + u1 * wbC[c][1];
                s0 += __shfl_xor_sync(0xFFFFFFFFu, s0, 1);
                s0 += __shfl_xor_sync(0xFFFFFFFFu, s0, 2);
                s1 += __shfl_xor_sync(0xFFFFFFFFu, s1, 1);
                s1 += __shfl_xor_sync(0xFFFFFFFFu, s1, 2);
                q0[c] = s0; q1[c] = s1;
            }

            if (qlid == 0) {
                pA[wid * 128 + 16 * i + quad]     = p0;
                pA[wid * 128 + 16 * i + quad + 8] = p1;
                #pragma unroll
                for (int c = 0; c < 3; ++c) {
                    pB[wid * 384 + c * 128 + 16 * i + quad]     = q0[c];
                    pB[wid * 384 + c * 128 + 16 * i + quad + 8] = q1[c];
                }
            }
        }
        __syncthreads();

        // ---- final: combine 16 warp partials, softmax, store ----
        if (tid < 128) {
            const int row = tid;
            float oa = s_b3a;
            float o0 = s_b3b0, o1 = s_b3b1, o2 = s_b3b2;
            #pragma unroll
            for (int w = 0; w < 16; ++w) {
                oa += pA[w * 128 + row];
                o0 += pB[w * 384 + row];
                o1 += pB[w * 384 + 128 + row];
                o2 += pB[w * 384 + 256 + row];
            }
            const float t0 = oa * o0, t1 = oa * o1, t2 = oa * o2;
            const float mx = fmaxf(t0, fmaxf(t1, t2));
            const float e0 = expf(t0 - mx), e1 = expf(t1 - mx), e2 = expf(t2 - mx);
            const float inv = 1.f / (e0 + e1 + e2);
            const int rg = t * 128 + row;
            out[rg * 3 + 0] = e0 * inv;
            out[rg * 3 + 1] = e1 * inv;
            out[rg * 3 + 2] = e2 * inv;
        }
        // next-tile partial writes are separated from these reads by the
        // h1 __syncthreads at the top of the next iteration.
    }
}

extern "C" void kernel_launch(void* const* d_in, const int* in_sizes, int n_in,
                              void* d_out, int out_size) {
    const float* x   = (const float*)d_in[0];
    const float* w1a = (const float*)d_in[1];
    const float* w1b = (const float*)d_in[2];
    const float* b1a = (const float*)d_in[3];
    const float* b1b = (const float*)d_in[4];
    const float* w2a = (const float*)d_in[5];
    const float* w2b = (const float*)d_in[6];
    const float* b2a = (const float*)d_in[7];
    const float* b2b = (const float*)d_in[8];
    const float* w3a = (const float*)d_in[9];
    const float* w3b = (const float*)d_in[10];
    const float* b3a = (const float*)d_in[11];
    const float* b3b = (const float*)d_in[12];
    float* out = (float*)d_out;

    int Bn = in_sizes[0] / 4;   // x is (2, B, 2) fp32

    cudaFuncSetAttribute(KroneNet_59485297049802_kernel,
                         cudaFuncAttributeMaxDynamicSharedMemorySize, SMEM_TOTAL);
    KroneNet_59485297049802_kernel<<<GRID, TPB, SMEM_TOTAL>>>(
        x, w1a, w1b, b1a, b1b, w2a, w2b, b2a, b2b, w3a, w3b, b3a, b3b, out, Bn);
}

// round 8
// speedup vs baseline: 1.4636x; 1.4636x over previous
#include <cuda_runtime.h>
#include <cuda_bf16.h>
#include <cstdint>

#define TPB  512
#define GRID 148

// ---- dynamic shared memory layout (bytes) ----
// h1 tiles: 128 rows x 128 bf16, padded row stride 272 B (conflict-free ldmatrix)
#define H1_STRIDE 272
#define H1A_OFF   0
#define H1B_OFF   34816                    // 128*272
#define PA_OFF    69632                    // 8 ngroups x 128 rows x f32    (4096)
#define PB_OFF    73728                    // 8 ngroups x 128 rows x float4 (16384)
#define SMEM_TOTAL 90112

static __device__ __forceinline__ uint32_t smem_u32(const void* p) {
    uint32_t a;
    asm("{ .reg .u64 t; cvta.to.shared.u64 t, %1; cvt.u32.u64 %0, t; }" : "=r"(a) : "l"(p));
    return a;
}

static __device__ __forceinline__ uint32_t pack_bf16(float a, float b) {
    __nv_bfloat162 t = __floats2bfloat162_rn(a, b);
    return *reinterpret_cast<uint32_t*>(&t);
}

static __device__ __forceinline__ void ldsm_x4(uint32_t a[4], uint32_t addr) {
    asm volatile("ldmatrix.sync.aligned.m8n8.x4.shared.b16 {%0,%1,%2,%3}, [%4];"
                 : "=r"(a[0]), "=r"(a[1]), "=r"(a[2]), "=r"(a[3]) : "r"(addr));
}

static __device__ __forceinline__ void mma16816(float c[4], const uint32_t a[4],
                                                uint32_t b0, uint32_t b1) {
    asm volatile(
        "mma.sync.aligned.m16n8k16.row.col.f32.bf16.bf16.f32 "
        "{%0,%1,%2,%3}, {%4,%5,%6,%7}, {%8,%9}, {%0,%1,%2,%3};"
        : "+f"(c[0]), "+f"(c[1]), "+f"(c[2]), "+f"(c[3])
        : "r"(a[0]), "r"(a[1]), "r"(a[2]), "r"(a[3]), "r"(b0), "r"(b1));
}

__global__ void __launch_bounds__(TPB, 1) KroneNet_59485297049802_kernel(
    const float* __restrict__ x,
    const float* __restrict__ w1a, const float* __restrict__ w1b,
    const float* __restrict__ b1a, const float* __restrict__ b1b,
    const float* __restrict__ w2a, const float* __restrict__ w2b,
    const float* __restrict__ b2a, const float* __restrict__ b2b,
    const float* __restrict__ w3a, const float* __restrict__ w3b,
    const float* __restrict__ b3a, const float* __restrict__ b3b,
    float* __restrict__ out, int Bn)
{
    extern __shared__ __align__(16) char sm[];
    const uint32_t smb = smem_u32(sm);
    const int tid  = threadIdx.x;
    const int wid  = tid >> 5;
    const int lane = tid & 31;
    const int quad = lane >> 2;    // 0..7
    const int qlid = lane & 3;     // 0..3

    // stream split: s = wid&1 (0 = stream a, 1 = stream b); ngroup = wid>>1
    const int s  = wid & 1;
    const int ng = wid >> 1;       // 0..7, n-cols [16ng, 16ng+16)

    float*  pA = reinterpret_cast<float*>(sm + PA_OFF);
    float4* pB = reinterpret_cast<float4*>(sm + PB_OFF);

    const float* w2s = s ? w2b : w2a;

    // ---- persistent B fragments (this stream only): n = 16ng + 8j + quad ----
    uint32_t Bf[2][8][2];
    #pragma unroll
    for (int j = 0; j < 2; ++j) {
        const int n = 16 * ng + 8 * j + quad;
        #pragma unroll
        for (int kk = 0; kk < 8; ++kk) {
            const int k0 = 16 * kk + 2 * qlid;
            float2 lo = *reinterpret_cast<const float2*>(w2s + n * 128 + k0);
            float2 hi = *reinterpret_cast<const float2*>(w2s + n * 128 + k0 + 8);
            Bf[j][kk][0] = pack_bf16(lo.x, lo.y);
            Bf[j][kk][1] = pack_bf16(hi.x, hi.y);
        }
    }

    // ---- epilogue constants: D cols n = 16ng + 8j + 2qlid + h ----
    // s==0: bias b2a + w3a (1 channel). s==1: bias b2b + w3b (3 channels).
    float biasC[2][2];
    float w3C[3][2][2];   // s==0 uses only [0]
    #pragma unroll
    for (int j = 0; j < 2; ++j)
        #pragma unroll
        for (int h = 0; h < 2; ++h) {
            const int n = 16 * ng + 8 * j + 2 * qlid + h;
            if (s == 0) {
                biasC[j][h]  = b2a[n];
                w3C[0][j][h] = w3a[n];
                w3C[1][j][h] = 0.f;
                w3C[2][j][h] = 0.f;
            } else {
                biasC[j][h]  = b2b[n];
                w3C[0][j][h] = w3b[n];
                w3C[1][j][h] = w3b[128 + n];
                w3C[2][j][h] = w3b[256 + n];
            }
        }
    const float s_b3a = b3a[0];
    const float s_b3b0 = b3b[0], s_b3b1 = b3b[1], s_b3b2 = b3b[2];

    // ---- layer-1 weights, packed bf16x2 (both streams, every warp does 8 rows) ----
    // lane l owns k in {2l, 2l+1} (pair 01) and {64+2l, 65+2l} (pair 23)
    __nv_bfloat162 pa0[2], pa1[2], pab[2], pb0[2], pb1[2], pbb[2];
    #pragma unroll
    for (int g = 0; g < 2; ++g) {
        const int k0 = (g << 6) + 2 * lane;      // first k of the pair
        pa0[g] = __floats2bfloat162_rn(w1a[2 * k0],     w1a[2 * (k0 + 1)]);
        pa1[g] = __floats2bfloat162_rn(w1a[2 * k0 + 1], w1a[2 * (k0 + 1) + 1]);
        pab[g] = __floats2bfloat162_rn(b1a[k0],         b1a[k0 + 1]);
        pb0[g] = __floats2bfloat162_rn(w1b[2 * k0],     w1b[2 * (k0 + 1)]);
        pb1[g] = __floats2bfloat162_rn(w1b[2 * k0 + 1], w1b[2 * (k0 + 1) + 1]);
        pbb[g] = __floats2bfloat162_rn(b1b[k0],         b1b[k0 + 1]);
    }

    // ldmatrix per-lane source address (m8n8.x4 over 16 rows x 16 cols bf16)
    const uint32_t lrow  = (uint32_t)((lane & 7) + ((lane >> 3) & 1) * 8);
    const uint32_t lcolb = (uint32_t)(((lane >> 4) & 1) * 16);
    const uint32_t aS = smb + (s ? H1B_OFF : H1A_OFF) + lrow * H1_STRIDE + lcolb;

    const int ntiles = Bn >> 7;
    const float2* x2 = reinterpret_cast<const float2*>(x);
    const __nv_bfloat162 z2 = __floats2bfloat162_rn(0.f, 0.f);

    for (int t = blockIdx.x; t < ntiles; t += gridDim.x) {
        // ---- layer 1: h1 = relu(W1 x + b1) -> bf16 SMEM (warp w: rows 8w..8w+7) ----
        #pragma unroll
        for (int r = 0; r < 8; ++r) {
            const int row = wid * 8 + r;
            const int rg  = t * 128 + row;
            const float2 xa = x2[rg];
            const float2 xb = x2[Bn + rg];
            const __nv_bfloat162 xax = __bfloat162bfloat162(__float2bfloat16(xa.x));
            const __nv_bfloat162 xay = __bfloat162bfloat162(__float2bfloat16(xa.y));
            const __nv_bfloat162 xbx = __bfloat162bfloat162(__float2bfloat16(xb.x));
            const __nv_bfloat162 xby = __bfloat162bfloat162(__float2bfloat16(xb.y));
            char* rowa = sm + H1A_OFF + row * H1_STRIDE;
            char* rowb = sm + H1B_OFF + row * H1_STRIDE;
            #pragma unroll
            for (int g = 0; g < 2; ++g) {
                __nv_bfloat162 ha = __hmax2(__hfma2(xax, pa0[g], __hfma2(xay, pa1[g], pab[g])), z2);
                __nv_bfloat162 hb = __hmax2(__hfma2(xbx, pb0[g], __hfma2(xby, pb1[g], pbb[g])), z2);
                *reinterpret_cast<uint32_t*>(rowa + 128 * g + 4 * lane) =
                    *reinterpret_cast<uint32_t*>(&ha);
                *reinterpret_cast<uint32_t*>(rowb + 128 * g + 4 * lane) =
                    *reinterpret_cast<uint32_t*>(&hb);
            }
        }
        __syncthreads();

        // ---- layer 2 (HMMA, own stream) + in-register epilogue ----
        #pragma unroll
        for (int i = 0; i < 8; ++i) {
            const uint32_t ibase = aS + (uint32_t)(i * 16 * H1_STRIDE);

            float c0[4] = {0.f, 0.f, 0.f, 0.f};
            float c1[4] = {0.f, 0.f, 0.f, 0.f};
            #pragma unroll
            for (int kk = 0; kk < 8; ++kk) {
                uint32_t af[4];
                ldsm_x4(af, ibase + 32u * kk);
                mma16816(c0, af, Bf[0][kk][0], Bf[0][kk][1]);
                mma16816(c1, af, Bf[1][kk][0], Bf[1][kk][1]);
            }

            // bias + relu
            const float v00 = fmaxf(c0[0] + biasC[0][0], 0.f);
            const float v01 = fmaxf(c0[1] + biasC[0][1], 0.f);
            const float v10 = fmaxf(c1[0] + biasC[1][0], 0.f);
            const float v11 = fmaxf(c1[1] + biasC[1][1], 0.f);
            const float u00 = fmaxf(c0[2] + biasC[0][0], 0.f);
            const float u01 = fmaxf(c0[3] + biasC[0][1], 0.f);
            const float u10 = fmaxf(c1[2] + biasC[1][0], 0.f);
            const float u11 = fmaxf(c1[3] + biasC[1][1], 0.f);

            if (s == 0) {
                float p0 = v00 * w3C[0][0][0] + v01 * w3C[0][0][1]
                         + v10 * w3C[0][1][0] + v11 * w3C[0][1][1];
                float p1 = u00 * w3C[0][0][0] + u01 * w3C[0][0][1]
                         + u10 * w3C[0][1][0] + u11 * w3C[0][1][1];
                p0 += __shfl_xor_sync(0xFFFFFFFFu, p0, 1);
                p0 += __shfl_xor_sync(0xFFFFFFFFu, p0, 2);
                p1 += __shfl_xor_sync(0xFFFFFFFFu, p1, 1);
                p1 += __shfl_xor_sync(0xFFFFFFFFu, p1, 2);
                if (qlid == 0) {
                    pA[ng * 128 + 16 * i + quad]     = p0;
                    pA[ng * 128 + 16 * i + quad + 8] = p1;
                }
            } else {
                float q0[3], q1[3];
                #pragma unroll
                for (int c = 0; c < 3; ++c) {
                    float s0 = v00 * w3C[c][0][0] + v01 * w3C[c][0][1]
                             + v10 * w3C[c][1][0] + v11 * w3C[c][1][1];
                    float s1 = u00 * w3C[c][0][0] + u01 * w3C[c][0][1]
                             + u10 * w3C[c][1][0] + u11 * w3C[c][1][1];
                    s0 += __shfl_xor_sync(0xFFFFFFFFu, s0, 1);
                    s0 += __shfl_xor_sync(0xFFFFFFFFu, s0, 2);
                    s1 += __shfl_xor_sync(0xFFFFFFFFu, s1, 1);
                    s1 += __shfl_xor_sync(0xFFFFFFFFu, s1, 2);
                    q0[c] = s0; q1[c] = s1;
                }
                if (qlid == 0) {
                    pB[ng * 128 + 16 * i + quad]     = make_float4(q0[0], q0[1], q0[2], 0.f);
                    pB[ng * 128 + 16 * i + quad + 8] = make_float4(q1[0], q1[1], q1[2], 0.f);
                }
            }
        }
        __syncthreads();

        // ---- final: combine 8 ngroup partials per stream, softmax, store ----
        if (tid < 128) {
            const int row = tid;
            float oa = s_b3a;
            float o0 = s_b3b0, o1 = s_b3b1, o2 = s_b3b2;
            #pragma unroll
            for (int g = 0; g < 8; ++g) {
                oa += pA[g * 128 + row];
                const float4 qb = pB[g * 128 + row];
                o0 += qb.x; o1 += qb.y; o2 += qb.z;
            }
            const float t0 = oa * o0, t1 = oa * o1, t2 = oa * o2;
            const float mx = fmaxf(t0, fmaxf(t1, t2));
            const float e0 = expf(t0 - mx), e1 = expf(t1 - mx), e2 = expf(t2 - mx);
            const float inv = 1.f / (e0 + e1 + e2);
            const int rg = t * 128 + row;
            out[rg * 3 + 0] = e0 * inv;
            out[rg * 3 + 1] = e1 * inv;
            out[rg * 3 + 2] = e2 * inv;
        }
        // next-tile pA/pB writes are separated from these reads by the
        // h1 __syncthreads at the top of the next iteration.
    }
}

extern "C" void kernel_launch(void* const* d_in, const int* in_sizes, int n_in,
                              void* d_out, int out_size) {
    const float* x   = (const float*)d_in[0];
    const float* w1a = (const float*)d_in[1];
    const float* w1b = (const float*)d_in[2];
    const float* b1a = (const float*)d_in[3];
    const float* b1b = (const float*)d_in[4];
    const float* w2a = (const float*)d_in[5];
    const float* w2b = (const float*)d_in[6];
    const float* b2a = (const float*)d_in[7];
    const float* b2b = (const float*)d_in[8];
    const float* w3a = (const float*)d_in[9];
    const float* w3b = (const float*)d_in[10];
    const float* b3a = (const float*)d_in[11];
    const float* b3b = (const float*)d_in[12];
    float* out = (float*)d_out;

    int Bn = in_sizes[0] / 4;   // x is (2, B, 2) fp32

    cudaFuncSetAttribute(KroneNet_59485297049802_kernel,
                         cudaFuncAttributeMaxDynamicSharedMemorySize, SMEM_TOTAL);
    KroneNet_59485297049802_kernel<<<GRID, TPB, SMEM_TOTAL>>>(
        x, w1a, w1b, b1a, b1b, w2a, w2b, b2a, b2b, w3a, w3b, b3a, b3b, out, Bn);
}